// round 16
// baseline (speedup 1.0000x reference)
#include <cuda_runtime.h>
#include <cuda_fp16.h>
#include <math.h>
#include <stdint.h>

// Problem constants
#define B_  2
#define T_  2048
#define C_  1024
#define U_  1024
#define H_  16
#define DH_ 64
#define M_  4096   // B_*T_

// Scratch (device globals; no allocation allowed)
__device__ __half g_Xh[(size_t)M_ * C_];        // x in fp16
__device__ __half g_Wth[3][(size_t)C_ * U_];    // W^T [N][K] fp16
__device__ __half g_Qh[(size_t)M_ * U_];        // Q fp16, pre-scaled by 0.125*log2(e)
__device__ __half g_Kh[(size_t)M_ * U_];        // K fp16 [t][U]
__device__ __half g_Vth[(size_t)M_ * U_];       // V fp16 transposed: [(b*H+h)*64+d][T]
__device__ float  g_O[(size_t)M_ * U_];
__device__ float  g_mask[M_];
__device__ __half g_maskh[M_];

__device__ __forceinline__ uint32_t smem_u32(const void* p) {
    uint32_t a;
    asm("{ .reg .u64 t; cvta.to.shared.u64 t, %1; cvt.u32.u64 %0, t; }"
        : "=r"(a) : "l"(p));
    return a;
}
__device__ __forceinline__ void cp_async16(uint32_t dst, const void* src) {
    asm volatile("cp.async.cg.shared.global [%0], [%1], 16;"
                 :: "r"(dst), "l"(src));
}
#define CP_COMMIT() asm volatile("cp.async.commit_group;" ::: "memory")
#define CP_WAIT(n)  asm volatile("cp.async.wait_group %0;" :: "n"(n) : "memory")

#define MMA_F16(d, a, b) \
    asm volatile("mma.sync.aligned.m16n8k16.row.col.f32.f16.f16.f32 " \
        "{%0,%1,%2,%3}, {%4,%5,%6,%7}, {%8,%9}, {%0,%1,%2,%3};" \
        : "+f"((d)[0]), "+f"((d)[1]), "+f"((d)[2]), "+f"((d)[3]) \
        : "r"((a)[0]), "r"((a)[1]), "r"((a)[2]), "r"((a)[3]), \
          "r"((b)[0]), "r"((b)[1]))

#define LDSM_X4(r0, r1, r2, r3, addr) \
    asm volatile("ldmatrix.sync.aligned.m8n8.x4.shared.b16 {%0,%1,%2,%3}, [%4];" \
        : "=r"(r0), "=r"(r1), "=r"(r2), "=r"(r3) : "r"(addr))

__device__ __forceinline__ uint32_t packh2(float lo, float hi) {
    __half2 h = __floats2half2_rn(lo, hi);
    return *reinterpret_cast<uint32_t*>(&h);
}
__device__ __forceinline__ uint32_t ex2h2(uint32_t t) {
    uint32_t r;
    asm("ex2.approx.f16x2 %0, %1;" : "=r"(r) : "r"(t));
    return r;
}
__device__ __forceinline__ uint32_t mulh2(uint32_t a, uint32_t b) {
    __half2 r = __hmul2(*reinterpret_cast<__half2*>(&a),
                        *reinterpret_cast<__half2*>(&b));
    return *reinterpret_cast<uint32_t*>(&r);
}

// ---------------------------------------------------------------------------
// x -> fp16 + row-sum mask (fused); one row per block
// ---------------------------------------------------------------------------
__global__ __launch_bounds__(128) void xconv_kernel(const float* __restrict__ x) {
    int row = blockIdx.x, tid = threadIdx.x;
    const float4* xr = reinterpret_cast<const float4*>(x + (size_t)row * C_);
    float4 a = xr[tid * 2], b = xr[tid * 2 + 1];
    float s = a.x + a.y + a.z + a.w + b.x + b.y + b.z + b.w;
    uint4 pk;
    pk.x = packh2(a.x, a.y); pk.y = packh2(a.z, a.w);
    pk.z = packh2(b.x, b.y); pk.w = packh2(b.z, b.w);
    *reinterpret_cast<uint4*>(g_Xh + (size_t)row * C_ + tid * 8) = pk;

    __shared__ float red[4];
#pragma unroll
    for (int o = 16; o; o >>= 1) s += __shfl_xor_sync(0xffffffffu, s, o);
    if ((tid & 31) == 0) red[tid >> 5] = s;
    __syncthreads();
    if (tid == 0) {
        float t = red[0] + red[1] + red[2] + red[3];
        float m = (t != 0.0f) ? 1.0f : 0.0f;
        g_mask[row] = m;
        g_maskh[row] = __float2half(m);
    }
}

// ---------------------------------------------------------------------------
// W [K,N] f32 -> Wt [N,K] fp16
// ---------------------------------------------------------------------------
__global__ __launch_bounds__(256) void wtrans_kernel(
    const float* __restrict__ Wq, const float* __restrict__ Wk,
    const float* __restrict__ Wv) {
    __shared__ float t[32][33];
    const float* W = blockIdx.z == 0 ? Wq : blockIdx.z == 1 ? Wk : Wv;
    __half* Wt = g_Wth[blockIdx.z];
    int x = blockIdx.x * 32 + threadIdx.x;
    int y0 = blockIdx.y * 32;
#pragma unroll
    for (int j = 0; j < 32; j += 8)
        t[threadIdx.y + j][threadIdx.x] = W[(size_t)(y0 + threadIdx.y + j) * U_ + x];
    __syncthreads();
    int ox = y0 + threadIdx.x;
    int oy0 = blockIdx.x * 32;
#pragma unroll
    for (int j = 0; j < 32; j += 8)
        Wt[(size_t)(oy0 + threadIdx.y + j) * C_ + ox] =
            __float2half(t[threadIdx.x][threadIdx.y + j]);
}

// ---------------------------------------------------------------------------
// QKV projection via mma.sync fp16 m16n8k16 + ldmatrix. Kc=32 (round-11
// variant: best measured). 2-stage ring, leading+trailing barrier.
// ---------------------------------------------------------------------------
#define KC    32
#define NCH   (C_ / KC)          // 32 chunks
#define QROWH 40                 // row stride in halves (80 B)
#define STGH  (2 * 128 * QROWH)  // halves per stage
#define QKV_SMEM (2 * STGH * 2)  // 40960 bytes

__global__ __launch_bounds__(256, 2) void qkv_mma_kernel(
    const float* __restrict__ bq, const float* __restrict__ bk,
    const float* __restrict__ bv) {
    extern __shared__ char smc[];
    uint32_t sb = smem_u32(smc);
    int tid = threadIdx.x;
    int wid = tid >> 5, lane = tid & 31;
    int gid = lane >> 2, tig = lane & 3;
    int lg = lane >> 3, lr = lane & 7;
    int wm = wid >> 2, wn = wid & 3;
    int sel = blockIdx.z;
    const __half* Wt = g_Wth[sel];
    const float* bias = sel == 0 ? bq : sel == 1 ? bk : bv;
    int n0 = blockIdx.x * 128, m0 = blockIdx.y * 128;

    int lrow = tid >> 1, lcb = (tid & 1) * 16;
    const __half* Ap = g_Xh + (size_t)(m0 + lrow) * C_ + lcb;
    const __half* Bp = Wt + (size_t)(n0 + lrow) * C_ + lcb;
    uint32_t adst = sb + (uint32_t)(lrow * QROWH + lcb) * 2;
    uint32_t bdst = adst + 128 * QROWH * 2;

    uint32_t aoff = (uint32_t)(((lg & 1) * 8 + lr) * (QROWH * 2) + (lg >> 1) * 16)
                    + (uint32_t)(wm * 64) * (QROWH * 2);
    uint32_t boff = (uint32_t)(((lg >> 1) * 8 + lr) * (QROWH * 2) + (lg & 1) * 16)
                    + (uint32_t)(wn * 32) * (QROWH * 2) + 128 * QROWH * 2;

    float acc[4][4][4];
#pragma unroll
    for (int i = 0; i < 4; i++)
#pragma unroll
        for (int j = 0; j < 4; j++)
#pragma unroll
            for (int r = 0; r < 4; r++) acc[i][j][r] = 0.0f;

    cp_async16(adst, Ap); cp_async16(adst + 16, Ap + 8);
    cp_async16(bdst, Bp); cp_async16(bdst + 16, Bp + 8);
    CP_COMMIT();

#pragma unroll 1
    for (int c = 0; c < NCH; c++) {
        if (c + 1 < NCH) {
            uint32_t so = ((c + 1) & 1) * STGH * 2;
            const __half* An = Ap + (c + 1) * KC;
            const __half* Bn = Bp + (c + 1) * KC;
            cp_async16(adst + so, An); cp_async16(adst + so + 16, An + 8);
            cp_async16(bdst + so, Bn); cp_async16(bdst + so + 16, Bn + 8);
            CP_COMMIT();
            CP_WAIT(1);
        } else {
            CP_WAIT(0);
        }
        __syncthreads();

        uint32_t stage = sb + (uint32_t)((c & 1) * STGH * 2);
#pragma unroll
        for (int ks = 0; ks < 2; ks++) {
            uint32_t kso = ks * 32;   // 16 halves
            uint32_t af[4][4];
#pragma unroll
            for (int mi = 0; mi < 4; mi++)
                LDSM_X4(af[mi][0], af[mi][1], af[mi][2], af[mi][3],
                        stage + aoff + mi * 16 * (QROWH * 2) + kso);
            uint32_t bf[4][2];
#pragma unroll
            for (int np = 0; np < 2; np++)
                LDSM_X4(bf[2 * np][0], bf[2 * np][1],
                        bf[2 * np + 1][0], bf[2 * np + 1][1],
                        stage + boff + np * 16 * (QROWH * 2) + kso);
#pragma unroll
            for (int mi = 0; mi < 4; mi++)
#pragma unroll
                for (int ni = 0; ni < 4; ni++)
                    MMA_F16(acc[mi][ni], af[mi], bf[ni]);
        }
        __syncthreads();
    }

    // Epilogue: bias + relu (+ CE prescale for Q). V stored transposed [d][t].
    float sc = (sel == 0) ? 0.18033688f : 1.0f;   // 0.125 * log2(e)
#pragma unroll
    for (int mi = 0; mi < 4; mi++) {
        int gr0 = m0 + wm * 64 + mi * 16 + gid;
#pragma unroll
        for (int ni = 0; ni < 4; ni++) {
            int gc = n0 + wn * 32 + ni * 8 + 2 * tig;
            float b0v = bias[gc], b1v = bias[gc + 1];
            float v00 = fmaxf(acc[mi][ni][0] + b0v, 0.0f) * sc;
            float v01 = fmaxf(acc[mi][ni][1] + b1v, 0.0f) * sc;
            float v10 = fmaxf(acc[mi][ni][2] + b0v, 0.0f) * sc;
            float v11 = fmaxf(acc[mi][ni][3] + b1v, 0.0f) * sc;
            if (sel == 2) {
                int bb = gr0 >> 11, tl = gr0 & (T_ - 1);
                int h = gc >> 6, d = gc & 63;
                __half* vp = g_Vth + ((size_t)(bb * H_ + h) * 64 + d) * T_;
                vp[tl] = __float2half(v00);
                vp[T_ + tl] = __float2half(v01);
                vp[tl + 8] = __float2half(v10);
                vp[T_ + tl + 8] = __float2half(v11);
            } else {
                __half* Y = (sel == 0 ? g_Qh : g_Kh);
                *reinterpret_cast<uint32_t*>(&Y[(size_t)gr0 * U_ + gc]) =
                    packh2(v00, v01);
                *reinterpret_cast<uint32_t*>(&Y[(size_t)(gr0 + 8) * U_ + gc]) =
                    packh2(v10, v11);
            }
        }
    }
}

// ---------------------------------------------------------------------------
// Flash-attention fp16, softmax-free, ldmatrix, software-pipelined:
// iteration kt computes S(kt) interleaved with PV(kt-1). LEADING barrier
// (cp.async visibility). K ring 3, V ring 4, mask ring 4.
// ---------------------------------------------------------------------------
#define KS_B(bb) ((bb) * 9216)            // 3 stages
#define VS_B(bb) (27648 + (bb) * 9216)    // 4 stages
#define MS_B(bb) (64512 + (bb) * 128)     // 4 stages
#define ATT_SMEM 65024
#define SPH 72   // tile row stride in halves (144 B)

__global__ __launch_bounds__(128, 3) void attn_mma_kernel() {
    extern __shared__ char smc[];
    uint32_t sb = smem_u32(smc);

    int tid = threadIdx.x;
    int lane = tid & 31;
    int gid = lane >> 2, tig = lane & 3;
    int lg = lane >> 3, lr = lane & 7;
    int qt = (int)gridDim.x - 1 - (int)blockIdx.x;   // big tiles first
    int bh = blockIdx.y;
    int b = bh >> 4;
    size_t baseU = (size_t)b * T_ * U_;
    int hcol = (bh & 15) * DH_;
    int qrow0 = (tid >> 5) * 16;

    int lrow = tid >> 1, lcb = (tid & 1) * 32;       // halves

    const __half* Kb = g_Kh + baseU + hcol + lcb;
    const __half* Vb = g_Vth + ((size_t)bh * 64 + lrow) * T_ + lcb;

    uint32_t ldoff = (uint32_t)(((lg >> 1) * 8 + lr) * (SPH * 2) + (lg & 1) * 16);
    uint32_t ldst = (uint32_t)(lrow * SPH + lcb) * 2;

    // prologue: tile 0 into stage 0
    {
        const __half* ks = Kb + (size_t)lrow * U_;
        uint32_t kd = sb + KS_B(0) + ldst;
        uint32_t vd = sb + VS_B(0) + ldst;
#pragma unroll
        for (int i = 0; i < 4; i++) {
            cp_async16(kd + i * 16, ks + i * 8);
            cp_async16(vd + i * 16, Vb + i * 8);
        }
        if (tid < 8)
            cp_async16(sb + MS_B(0) + tid * 16, g_maskh + b * T_ + tid * 8);
        CP_COMMIT();
    }

    // Q fragments (pre-scaled by CE)
    uint32_t aq[4][4];
    {
        int qg = qt * 64 + qrow0 + gid;
        const __half* q0 = g_Qh + baseU + (size_t)qg * U_ + hcol;
        const __half* q1 = q0 + 8 * U_;
#pragma unroll
        for (int ks = 0; ks < 4; ks++) {
            int kh = ks * 16 + 2 * tig;
            aq[ks][0] = *reinterpret_cast<const uint32_t*>(q0 + kh);
            aq[ks][1] = *reinterpret_cast<const uint32_t*>(q1 + kh);
            aq[ks][2] = *reinterpret_cast<const uint32_t*>(q0 + kh + 8);
            aq[ks][3] = *reinterpret_cast<const uint32_t*>(q1 + kh + 8);
        }
    }

    float o[8][4];
#pragma unroll
    for (int d = 0; d < 8; d++)
#pragma unroll
        for (int r = 0; r < 4; r++) o[d][r] = 0.0f;
    float lacc[4] = {0.0f, 0.0f, 0.0f, 0.0f};
    uint32_t ph[8][2];   // P of tile kt-1 (persists across iterations)

    int r0l = qrow0 + gid, r1l = r0l + 8;
    int kb = 0;          // K stage for current kt (mod 3)

#pragma unroll 1
    for (int kt = 0; kt <= qt; kt++) {
        int kbn = (kb == 2) ? 0 : kb + 1;
        if (kt < qt) {
            const __half* ksrc = Kb + (size_t)((kt + 1) * 64 + lrow) * U_;
            const __half* vsrc = Vb + (kt + 1) * 64;
            uint32_t kd = sb + KS_B(kbn) + ldst;
            uint32_t vd = sb + VS_B((kt + 1) & 3) + ldst;
#pragma unroll
            for (int i = 0; i < 4; i++) {
                cp_async16(kd + i * 16, ksrc + i * 8);
                cp_async16(vd + i * 16, vsrc + i * 8);
            }
            if (tid < 8)
                cp_async16(sb + MS_B((kt + 1) & 3) + tid * 16,
                           g_maskh + b * T_ + (kt + 1) * 64 + tid * 8);
            CP_COMMIT();
            CP_WAIT(1);
        } else {
            CP_WAIT(0);
        }
        __syncthreads();   // leading: tile kt from ALL threads visible

        uint32_t kbuf = sb + KS_B(kb) + ldoff;
        const uint32_t* Mh = reinterpret_cast<const uint32_t*>(smc + MS_B(kt & 3));

        // S(kt) interleaved with PV(kt-1)
        float s[8][4];
#pragma unroll
        for (int ni = 0; ni < 8; ni++)
#pragma unroll
            for (int r = 0; r < 4; r++) s[ni][r] = 0.0f;

        if (kt > 0) {
            uint32_t vbufp = sb + VS_B((kt - 1) & 3) + ldoff;
#pragma unroll
            for (int ks = 0; ks < 4; ks++) {
                uint32_t kso = ks * 32;
                uint32_t bfk[2][2], bfv[2][2];
                LDSM_X4(bfk[0][0], bfk[0][1], bfk[1][0], bfk[1][1],
                        kbuf + kso);
                uint32_t pa[4] = {ph[2 * ks][0], ph[2 * ks][1],
                                  ph[2 * ks + 1][0], ph[2 * ks + 1][1]};
                uint32_t onesb[2] = {0x3C003C00u, 0x3C003C00u};
                MMA_F16(lacc, pa, onesb);
#pragma unroll
                for (int np = 0; np < 4; np++) {
                    if (np) LDSM_X4(bfk[0][0], bfk[0][1], bfk[1][0], bfk[1][1],
                                    kbuf + np * 16 * (SPH * 2) + kso);
                    MMA_F16(s[2 * np], aq[ks], bfk[0]);
                    MMA_F16(s[2 * np + 1], aq[ks], bfk[1]);
                    LDSM_X4(bfv[0][0], bfv[0][1], bfv[1][0], bfv[1][1],
                            vbufp + np * 16 * (SPH * 2) + kso);
                    MMA_F16(o[2 * np], pa, bfv[0]);
                    MMA_F16(o[2 * np + 1], pa, bfv[1]);
                }
            }
        } else {
#pragma unroll
            for (int ks = 0; ks < 4; ks++) {
                uint32_t kso = ks * 32;
#pragma unroll
                for (int np = 0; np < 4; np++) {
                    uint32_t bf[2][2];
                    LDSM_X4(bf[0][0], bf[0][1], bf[1][0], bf[1][1],
                            kbuf + np * 16 * (SPH * 2) + kso);
                    MMA_F16(s[2 * np], aq[ks], bf[0]);
                    MMA_F16(s[2 * np + 1], aq[ks], bf[1]);
                }
            }
        }

        // P(kt) = exp2(s) * keymask (* causal on diag tile), packed half2
        bool diag = (kt == qt);
#pragma unroll
        for (int ni = 0; ni < 8; ni++) {
            int c0 = ni * 8 + 2 * tig;
            uint32_t km2 = Mh[c0 >> 1];
            uint32_t p0 = mulh2(ex2h2(packh2(s[ni][0], s[ni][1])), km2);
            uint32_t p1 = mulh2(ex2h2(packh2(s[ni][2], s[ni][3])), km2);
            if (diag) {
                uint32_t cm0 = packh2(c0 <= r0l ? 1.0f : 0.0f,
                                      c0 + 1 <= r0l ? 1.0f : 0.0f);
                uint32_t cm1 = packh2(c0 <= r1l ? 1.0f : 0.0f,
                                      c0 + 1 <= r1l ? 1.0f : 0.0f);
                p0 = mulh2(p0, cm0);
                p1 = mulh2(p1, cm1);
            }
            ph[ni][0] = p0;
            ph[ni][1] = p1;
        }
        kb = kbn;
    }

    // final PV(qt) — V stage (qt & 3) is still intact (no further issues)
    {
        uint32_t vbuf = sb + VS_B(qt & 3) + ldoff;
#pragma unroll
        for (int ks = 0; ks < 4; ks++) {
            uint32_t pa[4] = {ph[2 * ks][0], ph[2 * ks][1],
                              ph[2 * ks + 1][0], ph[2 * ks + 1][1]};
            uint32_t onesb[2] = {0x3C003C00u, 0x3C003C00u};
            MMA_F16(lacc, pa, onesb);
            uint32_t kso = ks * 32;
#pragma unroll
            for (int dp = 0; dp < 4; dp++) {
                uint32_t bf[2][2];
                LDSM_X4(bf[0][0], bf[0][1], bf[1][0], bf[1][1],
                        vbuf + dp * 16 * (SPH * 2) + kso);
                MMA_F16(o[2 * dp], pa, bf[0]);
                MMA_F16(o[2 * dp + 1], pa, bf[1]);
            }
        }
    }

    // epilogue: normalize by l, query mask, write f32 [q][d]
    {
        int qg0 = qt * 64 + qrow0 + gid;
        int qg1 = qg0 + 8;
        float inv0 = g_mask[b * T_ + qg0] / lacc[0];
        float inv1 = g_mask[b * T_ + qg1] / lacc[2];
        float* o0p = g_O + baseU + (size_t)qg0 * U_ + hcol;
        float* o1p = g_O + baseU + (size_t)qg1 * U_ + hcol;
#pragma unroll
        for (int d = 0; d < 8; d++) {
            int c = d * 8 + 2 * tig;
            *reinterpret_cast<float2*>(o0p + c) =
                make_float2(o[d][0] * inv0, o[d][1] * inv0);
            *reinterpret_cast<float2*>(o1p + c) =
                make_float2(o[d][2] * inv1, o[d][3] * inv1);
        }
    }
}

// ---------------------------------------------------------------------------
// Residual + LayerNorm (biased variance, eps=1e-8); one row per block
// ---------------------------------------------------------------------------
__global__ __launch_bounds__(256) void ln_kernel(
    const float* __restrict__ x, const float* __restrict__ gamma,
    const float* __restrict__ beta, float* __restrict__ out) {
    int row = blockIdx.x;
    int tid = threadIdx.x;
    __shared__ float rsum[8], rsq[8];
    __shared__ float smean, srstd;

    const float4* x4 = reinterpret_cast<const float4*>(x + (size_t)row * U_);
    const float4* o4 = reinterpret_cast<const float4*>(g_O + (size_t)row * U_);
    float4 xv = x4[tid], ov = o4[tid];
    float4 sv = make_float4(xv.x + ov.x, xv.y + ov.y, xv.z + ov.z, xv.w + ov.w);

    float s1 = sv.x + sv.y + sv.z + sv.w;
    float s2 = sv.x * sv.x + sv.y * sv.y + sv.z * sv.z + sv.w * sv.w;
#pragma unroll
    for (int o = 16; o; o >>= 1) {
        s1 += __shfl_xor_sync(0xffffffffu, s1, o);
        s2 += __shfl_xor_sync(0xffffffffu, s2, o);
    }
    if ((tid & 31) == 0) { rsum[tid >> 5] = s1; rsq[tid >> 5] = s2; }
    __syncthreads();
    if (tid == 0) {
        float t1 = 0, t2 = 0;
#pragma unroll
        for (int i = 0; i < 8; i++) { t1 += rsum[i]; t2 += rsq[i]; }
        float mean = t1 * (1.0f / U_);
        float var = t2 * (1.0f / U_) - mean * mean;
        smean = mean;
        srstd = rsqrtf(var + 1e-8f);
    }
    __syncthreads();
    float mean = smean, rstd = srstd;

    const float4* g4 = reinterpret_cast<const float4*>(gamma);
    const float4* b4 = reinterpret_cast<const float4*>(beta);
    float4 gv = g4[tid], bv = b4[tid];
    float4 o;
    o.x = gv.x * ((sv.x - mean) * rstd) + bv.x;
    o.y = gv.y * ((sv.y - mean) * rstd) + bv.y;
    o.z = gv.z * ((sv.z - mean) * rstd) + bv.z;
    o.w = gv.w * ((sv.w - mean) * rstd) + bv.w;
    reinterpret_cast<float4*>(out + (size_t)row * U_)[tid] = o;
}

// ---------------------------------------------------------------------------
extern "C" void kernel_launch(void* const* d_in, const int* in_sizes, int n_in,
                              void* d_out, int out_size) {
    const float* x     = (const float*)d_in[0];
    const float* Wq    = (const float*)d_in[1];
    const float* bq    = (const float*)d_in[2];
    const float* Wk    = (const float*)d_in[3];
    const float* bk    = (const float*)d_in[4];
    const float* Wv    = (const float*)d_in[5];
    const float* bv    = (const float*)d_in[6];
    const float* gamma = (const float*)d_in[7];
    const float* beta  = (const float*)d_in[8];
    float* out = (float*)d_out;

    cudaFuncSetAttribute(qkv_mma_kernel,
                         cudaFuncAttributeMaxDynamicSharedMemorySize, QKV_SMEM);
    cudaFuncSetAttribute(attn_mma_kernel,
                         cudaFuncAttributeMaxDynamicSharedMemorySize, ATT_SMEM);

    xconv_kernel<<<M_, 128>>>(x);
    wtrans_kernel<<<dim3(32, 32, 3), dim3(32, 8)>>>(Wq, Wk, Wv);
    qkv_mma_kernel<<<dim3(U_ / 128, M_ / 128, 3), 256, QKV_SMEM>>>(bq, bk, bv);
    attn_mma_kernel<<<dim3(T_ / 64, B_ * H_), 128, ATT_SMEM>>>();
    ln_kernel<<<M_, 256>>>(x, gamma, beta, out);
}

// round 17
// speedup vs baseline: 1.5183x; 1.5183x over previous
#include <cuda_runtime.h>
#include <cuda_fp16.h>
#include <math.h>
#include <stdint.h>

// Problem constants
#define B_  2
#define T_  2048
#define C_  1024
#define U_  1024
#define H_  16
#define DH_ 64
#define M_  4096   // B_*T_

// Scratch (device globals; no allocation allowed)
__device__ __half g_Xh[(size_t)M_ * C_];        // x in fp16
__device__ __half g_Wth[3][(size_t)C_ * U_];    // W^T [N][K] fp16
__device__ __half g_Qh[(size_t)M_ * U_];        // Q fp16, pre-scaled by 0.125*log2(e)
__device__ __half g_Kh[(size_t)M_ * U_];        // K fp16 [t][U]
__device__ __half g_Vth[(size_t)M_ * U_];       // V fp16 transposed: [(b*H+h)*64+d][T]
__device__ float  g_O[(size_t)M_ * U_];
__device__ float  g_mask[M_];
__device__ __half g_maskh[M_];

__device__ __forceinline__ uint32_t smem_u32(const void* p) {
    uint32_t a;
    asm("{ .reg .u64 t; cvta.to.shared.u64 t, %1; cvt.u32.u64 %0, t; }"
        : "=r"(a) : "l"(p));
    return a;
}
__device__ __forceinline__ void cp_async16(uint32_t dst, const void* src) {
    asm volatile("cp.async.cg.shared.global [%0], [%1], 16;"
                 :: "r"(dst), "l"(src));
}
#define CP_COMMIT() asm volatile("cp.async.commit_group;" ::: "memory")
#define CP_WAIT(n)  asm volatile("cp.async.wait_group %0;" :: "n"(n) : "memory")

#define MMA_F16(d, a, b) \
    asm volatile("mma.sync.aligned.m16n8k16.row.col.f32.f16.f16.f32 " \
        "{%0,%1,%2,%3}, {%4,%5,%6,%7}, {%8,%9}, {%0,%1,%2,%3};" \
        : "+f"((d)[0]), "+f"((d)[1]), "+f"((d)[2]), "+f"((d)[3]) \
        : "r"((a)[0]), "r"((a)[1]), "r"((a)[2]), "r"((a)[3]), \
          "r"((b)[0]), "r"((b)[1]))

#define LDSM_X4(r0, r1, r2, r3, addr) \
    asm volatile("ldmatrix.sync.aligned.m8n8.x4.shared.b16 {%0,%1,%2,%3}, [%4];" \
        : "=r"(r0), "=r"(r1), "=r"(r2), "=r"(r3) : "r"(addr))

__device__ __forceinline__ uint32_t packh2(float lo, float hi) {
    __half2 h = __floats2half2_rn(lo, hi);
    return *reinterpret_cast<uint32_t*>(&h);
}
__device__ __forceinline__ uint32_t ex2h2(uint32_t t) {
    uint32_t r;
    asm("ex2.approx.f16x2 %0, %1;" : "=r"(r) : "r"(t));
    return r;
}
__device__ __forceinline__ uint32_t mulh2(uint32_t a, uint32_t b) {
    __half2 r = __hmul2(*reinterpret_cast<__half2*>(&a),
                        *reinterpret_cast<__half2*>(&b));
    return *reinterpret_cast<uint32_t*>(&r);
}

// ---------------------------------------------------------------------------
// x -> fp16 + row-sum mask (fused); one row per block
// ---------------------------------------------------------------------------
__global__ __launch_bounds__(128) void xconv_kernel(const float* __restrict__ x) {
    int row = blockIdx.x, tid = threadIdx.x;
    const float4* xr = reinterpret_cast<const float4*>(x + (size_t)row * C_);
    float4 a = xr[tid * 2], b = xr[tid * 2 + 1];
    float s = a.x + a.y + a.z + a.w + b.x + b.y + b.z + b.w;
    uint4 pk;
    pk.x = packh2(a.x, a.y); pk.y = packh2(a.z, a.w);
    pk.z = packh2(b.x, b.y); pk.w = packh2(b.z, b.w);
    *reinterpret_cast<uint4*>(g_Xh + (size_t)row * C_ + tid * 8) = pk;

    __shared__ float red[4];
#pragma unroll
    for (int o = 16; o; o >>= 1) s += __shfl_xor_sync(0xffffffffu, s, o);
    if ((tid & 31) == 0) red[tid >> 5] = s;
    __syncthreads();
    if (tid == 0) {
        float t = red[0] + red[1] + red[2] + red[3];
        float m = (t != 0.0f) ? 1.0f : 0.0f;
        g_mask[row] = m;
        g_maskh[row] = __float2half(m);
    }
}

// ---------------------------------------------------------------------------
// W [K,N] f32 -> Wt [N,K] fp16
// ---------------------------------------------------------------------------
__global__ __launch_bounds__(256) void wtrans_kernel(
    const float* __restrict__ Wq, const float* __restrict__ Wk,
    const float* __restrict__ Wv) {
    __shared__ float t[32][33];
    const float* W = blockIdx.z == 0 ? Wq : blockIdx.z == 1 ? Wk : Wv;
    __half* Wt = g_Wth[blockIdx.z];
    int x = blockIdx.x * 32 + threadIdx.x;
    int y0 = blockIdx.y * 32;
#pragma unroll
    for (int j = 0; j < 32; j += 8)
        t[threadIdx.y + j][threadIdx.x] = W[(size_t)(y0 + threadIdx.y + j) * U_ + x];
    __syncthreads();
    int ox = y0 + threadIdx.x;
    int oy0 = blockIdx.x * 32;
#pragma unroll
    for (int j = 0; j < 32; j += 8)
        Wt[(size_t)(oy0 + threadIdx.y + j) * C_ + ox] =
            __float2half(t[threadIdx.x][threadIdx.y + j]);
}

// ---------------------------------------------------------------------------
// QKV projection via mma.sync fp16 m16n8k16 + ldmatrix. Kc=32.
// 2-stage ring, leading+trailing barrier.
// ---------------------------------------------------------------------------
#define KC    32
#define NCH   (C_ / KC)          // 32 chunks
#define QROWH 40                 // row stride in halves (80 B)
#define STGH  (2 * 128 * QROWH)  // halves per stage
#define QKV_SMEM (2 * STGH * 2)  // 40960 bytes

__global__ __launch_bounds__(256, 2) void qkv_mma_kernel(
    const float* __restrict__ bq, const float* __restrict__ bk,
    const float* __restrict__ bv) {
    extern __shared__ char smc[];
    uint32_t sb = smem_u32(smc);
    int tid = threadIdx.x;
    int wid = tid >> 5, lane = tid & 31;
    int gid = lane >> 2, tig = lane & 3;
    int lg = lane >> 3, lr = lane & 7;
    int wm = wid >> 2, wn = wid & 3;
    int sel = blockIdx.z;
    const __half* Wt = g_Wth[sel];
    const float* bias = sel == 0 ? bq : sel == 1 ? bk : bv;
    int n0 = blockIdx.x * 128, m0 = blockIdx.y * 128;

    int lrow = tid >> 1, lcb = (tid & 1) * 16;
    const __half* Ap = g_Xh + (size_t)(m0 + lrow) * C_ + lcb;
    const __half* Bp = Wt + (size_t)(n0 + lrow) * C_ + lcb;
    uint32_t adst = sb + (uint32_t)(lrow * QROWH + lcb) * 2;
    uint32_t bdst = adst + 128 * QROWH * 2;

    uint32_t aoff = (uint32_t)(((lg & 1) * 8 + lr) * (QROWH * 2) + (lg >> 1) * 16)
                    + (uint32_t)(wm * 64) * (QROWH * 2);
    uint32_t boff = (uint32_t)(((lg >> 1) * 8 + lr) * (QROWH * 2) + (lg & 1) * 16)
                    + (uint32_t)(wn * 32) * (QROWH * 2) + 128 * QROWH * 2;

    float acc[4][4][4];
#pragma unroll
    for (int i = 0; i < 4; i++)
#pragma unroll
        for (int j = 0; j < 4; j++)
#pragma unroll
            for (int r = 0; r < 4; r++) acc[i][j][r] = 0.0f;

    cp_async16(adst, Ap); cp_async16(adst + 16, Ap + 8);
    cp_async16(bdst, Bp); cp_async16(bdst + 16, Bp + 8);
    CP_COMMIT();

#pragma unroll 1
    for (int c = 0; c < NCH; c++) {
        if (c + 1 < NCH) {
            uint32_t so = ((c + 1) & 1) * STGH * 2;
            const __half* An = Ap + (c + 1) * KC;
            const __half* Bn = Bp + (c + 1) * KC;
            cp_async16(adst + so, An); cp_async16(adst + so + 16, An + 8);
            cp_async16(bdst + so, Bn); cp_async16(bdst + so + 16, Bn + 8);
            CP_COMMIT();
            CP_WAIT(1);
        } else {
            CP_WAIT(0);
        }
        __syncthreads();

        uint32_t stage = sb + (uint32_t)((c & 1) * STGH * 2);
#pragma unroll
        for (int ks = 0; ks < 2; ks++) {
            uint32_t kso = ks * 32;   // 16 halves
            uint32_t af[4][4];
#pragma unroll
            for (int mi = 0; mi < 4; mi++)
                LDSM_X4(af[mi][0], af[mi][1], af[mi][2], af[mi][3],
                        stage + aoff + mi * 16 * (QROWH * 2) + kso);
            uint32_t bf[4][2];
#pragma unroll
            for (int np = 0; np < 2; np++)
                LDSM_X4(bf[2 * np][0], bf[2 * np][1],
                        bf[2 * np + 1][0], bf[2 * np + 1][1],
                        stage + boff + np * 16 * (QROWH * 2) + kso);
#pragma unroll
            for (int mi = 0; mi < 4; mi++)
#pragma unroll
                for (int ni = 0; ni < 4; ni++)
                    MMA_F16(acc[mi][ni], af[mi], bf[ni]);
        }
        __syncthreads();
    }

    // Epilogue: bias + relu (+ CE prescale for Q). V stored transposed [d][t].
    float sc = (sel == 0) ? 0.18033688f : 1.0f;   // 0.125 * log2(e)
#pragma unroll
    for (int mi = 0; mi < 4; mi++) {
        int gr0 = m0 + wm * 64 + mi * 16 + gid;
#pragma unroll
        for (int ni = 0; ni < 4; ni++) {
            int gc = n0 + wn * 32 + ni * 8 + 2 * tig;
            float b0v = bias[gc], b1v = bias[gc + 1];
            float v00 = fmaxf(acc[mi][ni][0] + b0v, 0.0f) * sc;
            float v01 = fmaxf(acc[mi][ni][1] + b1v, 0.0f) * sc;
            float v10 = fmaxf(acc[mi][ni][2] + b0v, 0.0f) * sc;
            float v11 = fmaxf(acc[mi][ni][3] + b1v, 0.0f) * sc;
            if (sel == 2) {
                int bb = gr0 >> 11, tl = gr0 & (T_ - 1);
                int h = gc >> 6, d = gc & 63;
                __half* vp = g_Vth + ((size_t)(bb * H_ + h) * 64 + d) * T_;
                vp[tl] = __float2half(v00);
                vp[T_ + tl] = __float2half(v01);
                vp[tl + 8] = __float2half(v10);
                vp[T_ + tl + 8] = __float2half(v11);
            } else {
                __half* Y = (sel == 0 ? g_Qh : g_Kh);
                *reinterpret_cast<uint32_t*>(&Y[(size_t)gr0 * U_ + gc]) =
                    packh2(v00, v01);
                *reinterpret_cast<uint32_t*>(&Y[(size_t)(gr0 + 8) * U_ + gc]) =
                    packh2(v10, v11);
            }
        }
    }
}

// ---------------------------------------------------------------------------
// Flash-attention fp16, softmax-free, ldmatrix, software-pipelined:
// iteration kt computes S(kt) interleaved with PV(kt-1). LEADING barrier
// (cp.async visibility). K ring 3, V ring 4, mask ring 4.
// ---------------------------------------------------------------------------
#define KS_B(bb) ((bb) * 9216)            // 3 stages
#define VS_B(bb) (27648 + (bb) * 9216)    // 4 stages
#define MS_B(bb) (64512 + (bb) * 128)     // 4 stages
#define ATT_SMEM 65024
#define SPH 72   // tile row stride in halves (144 B)

__global__ __launch_bounds__(128, 3) void attn_mma_kernel() {
    extern __shared__ char smc[];
    uint32_t sb = smem_u32(smc);

    int tid = threadIdx.x;
    int lane = tid & 31;
    int gid = lane >> 2, tig = lane & 3;
    int lg = lane >> 3, lr = lane & 7;
    int qt = (int)gridDim.x - 1 - (int)blockIdx.x;   // big tiles first
    int bh = blockIdx.y;
    int b = bh >> 4;
    size_t baseU = (size_t)b * T_ * U_;
    int hcol = (bh & 15) * DH_;
    int qrow0 = (tid >> 5) * 16;

    int lrow = tid >> 1, lcb = (tid & 1) * 32;       // halves

    const __half* Kb = g_Kh + baseU + hcol + lcb;
    const __half* Vb = g_Vth + ((size_t)bh * 64 + lrow) * T_ + lcb;

    uint32_t ldoff = (uint32_t)(((lg >> 1) * 8 + lr) * (SPH * 2) + (lg & 1) * 16);
    uint32_t ldst = (uint32_t)(lrow * SPH + lcb) * 2;

    // prologue: tile 0 into stage 0
    {
        const __half* ks = Kb + (size_t)lrow * U_;
        uint32_t kd = sb + KS_B(0) + ldst;
        uint32_t vd = sb + VS_B(0) + ldst;
#pragma unroll
        for (int i = 0; i < 4; i++) {
            cp_async16(kd + i * 16, ks + i * 8);
            cp_async16(vd + i * 16, Vb + i * 8);
        }
        if (tid < 8)
            cp_async16(sb + MS_B(0) + tid * 16, g_maskh + b * T_ + tid * 8);
        CP_COMMIT();
    }

    // Q fragments (pre-scaled by CE)
    uint32_t aq[4][4];
    {
        int qg = qt * 64 + qrow0 + gid;
        const __half* q0 = g_Qh + baseU + (size_t)qg * U_ + hcol;
        const __half* q1 = q0 + 8 * U_;
#pragma unroll
        for (int ks = 0; ks < 4; ks++) {
            int kh = ks * 16 + 2 * tig;
            aq[ks][0] = *reinterpret_cast<const uint32_t*>(q0 + kh);
            aq[ks][1] = *reinterpret_cast<const uint32_t*>(q1 + kh);
            aq[ks][2] = *reinterpret_cast<const uint32_t*>(q0 + kh + 8);
            aq[ks][3] = *reinterpret_cast<const uint32_t*>(q1 + kh + 8);
        }
    }

    float o[8][4];
#pragma unroll
    for (int d = 0; d < 8; d++)
#pragma unroll
        for (int r = 0; r < 4; r++) o[d][r] = 0.0f;
    float lacc[4] = {0.0f, 0.0f, 0.0f, 0.0f};
    uint32_t ph[8][2];   // P of tile kt-1 (persists across iterations)

    int r0l = qrow0 + gid, r1l = r0l + 8;
    int kb = 0;          // K stage for current kt (mod 3)

#pragma unroll 1
    for (int kt = 0; kt <= qt; kt++) {
        int kbn = (kb == 2) ? 0 : kb + 1;
        if (kt < qt) {
            const __half* ksrc = Kb + (size_t)((kt + 1) * 64 + lrow) * U_;
            const __half* vsrc = Vb + (kt + 1) * 64;
            uint32_t kd = sb + KS_B(kbn) + ldst;
            uint32_t vd = sb + VS_B((kt + 1) & 3) + ldst;
#pragma unroll
            for (int i = 0; i < 4; i++) {
                cp_async16(kd + i * 16, ksrc + i * 8);
                cp_async16(vd + i * 16, vsrc + i * 8);
            }
            if (tid < 8)
                cp_async16(sb + MS_B((kt + 1) & 3) + tid * 16,
                           g_maskh + b * T_ + (kt + 1) * 64 + tid * 8);
            CP_COMMIT();
            CP_WAIT(1);
        } else {
            CP_WAIT(0);
        }
        __syncthreads();   // leading: tile kt from ALL threads visible

        uint32_t kbuf = sb + KS_B(kb) + ldoff;
        const uint32_t* Mh = reinterpret_cast<const uint32_t*>(smc + MS_B(kt & 3));

        // S(kt) interleaved with PV(kt-1)
        float s[8][4];
#pragma unroll
        for (int ni = 0; ni < 8; ni++)
#pragma unroll
            for (int r = 0; r < 4; r++) s[ni][r] = 0.0f;

        if (kt > 0) {
            uint32_t vbufp = sb + VS_B((kt - 1) & 3) + ldoff;
#pragma unroll
            for (int ks = 0; ks < 4; ks++) {
                uint32_t kso = ks * 32;
                uint32_t bfk[2][2], bfv[2][2];
                LDSM_X4(bfk[0][0], bfk[0][1], bfk[1][0], bfk[1][1],
                        kbuf + kso);
                uint32_t pa[4] = {ph[2 * ks][0], ph[2 * ks][1],
                                  ph[2 * ks + 1][0], ph[2 * ks + 1][1]};
                uint32_t onesb[2] = {0x3C003C00u, 0x3C003C00u};
                MMA_F16(lacc, pa, onesb);
#pragma unroll
                for (int np = 0; np < 4; np++) {
                    if (np) LDSM_X4(bfk[0][0], bfk[0][1], bfk[1][0], bfk[1][1],
                                    kbuf + np * 16 * (SPH * 2) + kso);
                    MMA_F16(s[2 * np], aq[ks], bfk[0]);
                    MMA_F16(s[2 * np + 1], aq[ks], bfk[1]);
                    LDSM_X4(bfv[0][0], bfv[0][1], bfv[1][0], bfv[1][1],
                            vbufp + np * 16 * (SPH * 2) + kso);
                    MMA_F16(o[2 * np], pa, bfv[0]);
                    MMA_F16(o[2 * np + 1], pa, bfv[1]);
                }
            }
        } else {
#pragma unroll
            for (int ks = 0; ks < 4; ks++) {
                uint32_t kso = ks * 32;
#pragma unroll
                for (int np = 0; np < 4; np++) {
                    uint32_t bf[2][2];
                    LDSM_X4(bf[0][0], bf[0][1], bf[1][0], bf[1][1],
                            kbuf + np * 16 * (SPH * 2) + kso);
                    MMA_F16(s[2 * np], aq[ks], bf[0]);
                    MMA_F16(s[2 * np + 1], aq[ks], bf[1]);
                }
            }
        }

        // P(kt) = exp2(s) * keymask (* causal on diag tile), packed half2
        bool diag = (kt == qt);
#pragma unroll
        for (int ni = 0; ni < 8; ni++) {
            int c0 = ni * 8 + 2 * tig;
            uint32_t km2 = Mh[c0 >> 1];
            uint32_t p0 = mulh2(ex2h2(packh2(s[ni][0], s[ni][1])), km2);
            uint32_t p1 = mulh2(ex2h2(packh2(s[ni][2], s[ni][3])), km2);
            if (diag) {
                uint32_t cm0 = packh2(c0 <= r0l ? 1.0f : 0.0f,
                                      c0 + 1 <= r0l ? 1.0f : 0.0f);
                uint32_t cm1 = packh2(c0 <= r1l ? 1.0f : 0.0f,
                                      c0 + 1 <= r1l ? 1.0f : 0.0f);
                p0 = mulh2(p0, cm0);
                p1 = mulh2(p1, cm1);
            }
            ph[ni][0] = p0;
            ph[ni][1] = p1;
        }
        kb = kbn;
    }

    // final PV(qt) — V stage (qt & 3) is still intact (no further issues)
    {
        uint32_t vbuf = sb + VS_B(qt & 3) + ldoff;
#pragma unroll
        for (int ks = 0; ks < 4; ks++) {
            uint32_t pa[4] = {ph[2 * ks][0], ph[2 * ks][1],
                              ph[2 * ks + 1][0], ph[2 * ks + 1][1]};
            uint32_t onesb[2] = {0x3C003C00u, 0x3C003C00u};
            MMA_F16(lacc, pa, onesb);
            uint32_t kso = ks * 32;
#pragma unroll
            for (int dp = 0; dp < 4; dp++) {
                uint32_t bf[2][2];
                LDSM_X4(bf[0][0], bf[0][1], bf[1][0], bf[1][1],
                        vbuf + dp * 16 * (SPH * 2) + kso);
                MMA_F16(o[2 * dp], pa, bf[0]);
                MMA_F16(o[2 * dp + 1], pa, bf[1]);
            }
        }
    }

    // epilogue: normalize by l, query mask, write f32 [q][d]
    {
        int qg0 = qt * 64 + qrow0 + gid;
        int qg1 = qg0 + 8;
        float inv0 = g_mask[b * T_ + qg0] / lacc[0];
        float inv1 = g_mask[b * T_ + qg1] / lacc[2];
        float* o0p = g_O + baseU + (size_t)qg0 * U_ + hcol;
        float* o1p = g_O + baseU + (size_t)qg1 * U_ + hcol;
#pragma unroll
        for (int d = 0; d < 8; d++) {
            int c = d * 8 + 2 * tig;
            *reinterpret_cast<float2*>(o0p + c) =
                make_float2(o[d][0] * inv0, o[d][1] * inv0);
            *reinterpret_cast<float2*>(o1p + c) =
                make_float2(o[d][2] * inv1, o[d][3] * inv1);
        }
    }
}

// ---------------------------------------------------------------------------
// Residual + LayerNorm (biased variance, eps=1e-8); one row per block
// ---------------------------------------------------------------------------
__global__ __launch_bounds__(256) void ln_kernel(
    const float* __restrict__ x, const float* __restrict__ gamma,
    const float* __restrict__ beta, float* __restrict__ out) {
    int row = blockIdx.x;
    int tid = threadIdx.x;
    __shared__ float rsum[8], rsq[8];
    __shared__ float smean, srstd;

    const float4* x4 = reinterpret_cast<const float4*>(x + (size_t)row * U_);
    const float4* o4 = reinterpret_cast<const float4*>(g_O + (size_t)row * U_);
    float4 xv = x4[tid], ov = o4[tid];
    float4 sv = make_float4(xv.x + ov.x, xv.y + ov.y, xv.z + ov.z, xv.w + ov.w);

    float s1 = sv.x + sv.y + sv.z + sv.w;
    float s2 = sv.x * sv.x + sv.y * sv.y + sv.z * sv.z + sv.w * sv.w;
#pragma unroll
    for (int o = 16; o; o >>= 1) {
        s1 += __shfl_xor_sync(0xffffffffu, s1, o);
        s2 += __shfl_xor_sync(0xffffffffu, s2, o);
    }
    if ((tid & 31) == 0) { rsum[tid >> 5] = s1; rsq[tid >> 5] = s2; }
    __syncthreads();
    if (tid == 0) {
        float t1 = 0, t2 = 0;
#pragma unroll
        for (int i = 0; i < 8; i++) { t1 += rsum[i]; t2 += rsq[i]; }
        float mean = t1 * (1.0f / U_);
        float var = t2 * (1.0f / U_) - mean * mean;
        smean = mean;
        srstd = rsqrtf(var + 1e-8f);
    }
    __syncthreads();
    float mean = smean, rstd = srstd;

    const float4* g4 = reinterpret_cast<const float4*>(gamma);
    const float4* b4 = reinterpret_cast<const float4*>(beta);
    float4 gv = g4[tid], bv = b4[tid];
    float4 o;
    o.x = gv.x * ((sv.x - mean) * rstd) + bv.x;
    o.y = gv.y * ((sv.y - mean) * rstd) + bv.y;
    o.z = gv.z * ((sv.z - mean) * rstd) + bv.z;
    o.w = gv.w * ((sv.w - mean) * rstd) + bv.w;
    reinterpret_cast<float4*>(out + (size_t)row * U_)[tid] = o;
}

// ---------------------------------------------------------------------------
extern "C" void kernel_launch(void* const* d_in, const int* in_sizes, int n_in,
                              void* d_out, int out_size) {
    const float* x     = (const float*)d_in[0];
    const float* Wq    = (const float*)d_in[1];
    const float* bq    = (const float*)d_in[2];
    const float* Wk    = (const float*)d_in[3];
    const float* bk    = (const float*)d_in[4];
    const float* Wv    = (const float*)d_in[5];
    const float* bv    = (const float*)d_in[6];
    const float* gamma = (const float*)d_in[7];
    const float* beta  = (const float*)d_in[8];
    float* out = (float*)d_out;

    cudaFuncSetAttribute(qkv_mma_kernel,
                         cudaFuncAttributeMaxDynamicSharedMemorySize, QKV_SMEM);
    cudaFuncSetAttribute(attn_mma_kernel,
                         cudaFuncAttributeMaxDynamicSharedMemorySize, ATT_SMEM);

    xconv_kernel<<<M_, 128>>>(x);
    wtrans_kernel<<<dim3(32, 32, 3), dim3(32, 8)>>>(Wq, Wk, Wv);
    qkv_mma_kernel<<<dim3(U_ / 128, M_ / 128, 3), 256, QKV_SMEM>>>(bq, bk, bv);
    attn_mma_kernel<<<dim3(T_ / 64, B_ * H_), 128, ATT_SMEM>>>();
    ln_kernel<<<M_, 256>>>(x, gamma, beta, out);
}